// round 1
// baseline (speedup 1.0000x reference)
#include <cuda_runtime.h>
#include <cstdint>

#define NN 50000
#define MM 128
#define EE 800000
#define KAPPA 0.99f
#define FTOL 3e-6f
#define NPAD (NN + 32)

// ---------------- device scratch (no allocations allowed) ----------------
__device__ float g_WpT[MM * MM];      // [k][m] = Wp[m][k]
__device__ float g_O1T[MM * MM];      // [p][m] = Omega1[m][p]
__device__ float g_X[(size_t)NPAD * MM];   // node-major state (also temp for U^T)
__device__ float g_Y[(size_t)NPAD * MM];   // node-major Wp@X result
__device__ float g_B[(size_t)NPAD * MM];   // node-major bias
__device__ int   g_colptr[NN + 1];
__device__ int   g_cursor[NN];
__device__ int   g_csc_row[EE];
__device__ float g_csc_val[EE];
__device__ int   g_bsum[64];
__device__ unsigned g_err_bits;
__device__ int   g_converged;

// ---------------- projection: row-wise L1-ball projection of W ----------------
__global__ void k_project(const float* __restrict__ W) {
    int r = blockIdx.x;      // row of W
    int t = threadIdx.x;     // 128 threads
    __shared__ float a[128];
    __shared__ float c[128];
    __shared__ float s_css[128];
    __shared__ int s_rho;

    float w = W[r * MM + t];
    a[t] = fabsf(w);
    // bitonic sort DESCENDING (n=128)
    for (int k = 2; k <= 128; k <<= 1) {
        for (int j = k >> 1; j > 0; j >>= 1) {
            __syncthreads();
            int p = t ^ j;
            if (p > t) {
                float x = a[t], y = a[p];
                bool desc = ((t & k) == 0);
                if (desc ? (x < y) : (x > y)) { a[t] = y; a[p] = x; }
            }
        }
    }
    __syncthreads();
    // inclusive scan of sorted values
    c[t] = a[t];
    for (int off = 1; off < 128; off <<= 1) {
        __syncthreads();
        float v = (t >= off) ? c[t - off] : 0.f;
        __syncthreads();
        c[t] += v;
    }
    __syncthreads();
    float row_l1 = c[127];
    float css = c[t] - KAPPA;
    s_css[t] = css;
    if (t == 0) s_rho = 0;
    __syncthreads();
    if (a[t] * (float)(t + 1) > css) atomicAdd(&s_rho, 1);
    __syncthreads();
    int rho = s_rho;
    float alpha = s_css[rho - 1] / (float)rho;
    float pw;
    if (row_l1 > KAPPA) {
        float m = fabsf(w) - alpha;
        if (m < 0.f) m = 0.f;
        pw = (w > 0.f) ? m : ((w < 0.f) ? -m : 0.f);
    } else {
        pw = w;
    }
    g_WpT[t * MM + r] = pw;   // transposed: [k][m]
}

// ---------------- generic tiled transpose: dst[c*R+r] = src[r*C+c] ----------------
__global__ void k_transpose(const float* __restrict__ src, float* __restrict__ dst,
                            int R, int C) {
    __shared__ float tile[32][33];
    int c0 = blockIdx.x * 32, r0 = blockIdx.y * 32;
    int tx = threadIdx.x, ty = threadIdx.y; // (32,8)
#pragma unroll
    for (int q = 0; q < 4; ++q) {
        int r = r0 + ty + q * 8, c = c0 + tx;
        if (r < R && c < C) tile[ty + q * 8][tx] = src[(size_t)r * C + c];
    }
    __syncthreads();
#pragma unroll
    for (int q = 0; q < 4; ++q) {
        int c = c0 + ty + q * 8, r = r0 + tx;
        if (c < C && r < R) dst[(size_t)c * R + r] = tile[tx][ty + q * 8];
    }
}

// ---------------- CSC build ----------------
__global__ void k_csc_init() {
    int i = blockIdx.x * blockDim.x + threadIdx.x;
    if (i <= NN) g_colptr[i] = 0;
    if (i < NN) g_cursor[i] = 0;
}
__global__ void k_hist(const int* __restrict__ ecol) {
    int i = blockIdx.x * blockDim.x + threadIdx.x;
    if (i < EE) atomicAdd(&g_colptr[ecol[i] + 1], 1);
}
__global__ void k_scan1() {
    __shared__ int s[1024];
    int t = threadIdx.x;
    int i = blockIdx.x * 1024 + t;
    int v = (i < NN) ? g_colptr[1 + i] : 0;
    s[t] = v;
    for (int off = 1; off < 1024; off <<= 1) {
        __syncthreads();
        int u = (t >= off) ? s[t - off] : 0;
        __syncthreads();
        s[t] += u;
    }
    __syncthreads();
    if (i < NN) g_colptr[1 + i] = s[t];
    if (t == 1023) g_bsum[blockIdx.x] = s[1023];
}
__global__ void k_scan2() {
    int run = 0;
    for (int b = 0; b < 49; ++b) { int v = g_bsum[b]; g_bsum[b] = run; run += v; }
}
__global__ void k_scan3() {
    int i = blockIdx.x * 1024 + threadIdx.x;
    if (i < NN) g_colptr[1 + i] += g_bsum[blockIdx.x];
}
__global__ void k_scatter(const int* __restrict__ erow, const int* __restrict__ ecol,
                          const float* __restrict__ eval) {
    int i = blockIdx.x * blockDim.x + threadIdx.x;
    if (i >= EE) return;
    int c = ecol[i];
    int p = atomicAdd(&g_cursor[c], 1);
    int idx = g_colptr[c] + p;
    g_csc_row[idx] = erow[i];
    g_csc_val[idx] = eval[i];
}

// ---------------- GEMM: Out[n][m] = sum_k A[n][k] * Wt[k][m] ----------------
// block: 256 threads, 32 nodes/block, full M=128. dyn smem: 64KB W + 16.9KB X
#define GEMM_SMEM (65536 + 32 * 33 * 16)
__global__ void __launch_bounds__(256) k_gemm(const float* __restrict__ A,
                                              const float* __restrict__ Wt,
                                              float* __restrict__ Out, int guarded) {
    if (guarded && g_converged) return;
    extern __shared__ unsigned char smem[];
    float4* ws4 = (float4*)smem;                    // [128][32]
    float4* xs4 = (float4*)(smem + 65536);          // [32][33]
    float*  xsf = (float*)xs4;
    int tid = threadIdx.x;
    // load full W (transposed layout [k][m]) into shared
#pragma unroll
    for (int i = tid; i < 128 * 32; i += 256) {
        ws4[i] = ((const float4*)Wt)[i];
    }
    int n0 = blockIdx.x * 32;
#pragma unroll
    for (int i = tid; i < 32 * 32; i += 256) {
        int r = i >> 5, c = i & 31;
        xs4[r * 33 + c] = ((const float4*)A)[(size_t)(n0 + r) * 32 + c];
    }
    __syncthreads();
    int tx = tid & 31;   // m-group: m = tx*4 + j
    int ty = tid >> 5;   // node group: n = n0 + ty*4 + i
    float acc[4][4];
#pragma unroll
    for (int i = 0; i < 4; ++i)
#pragma unroll
        for (int j = 0; j < 4; ++j) acc[i][j] = 0.f;

    const float* x0 = &xsf[(ty * 4 + 0) * 132];
    const float* x1 = &xsf[(ty * 4 + 1) * 132];
    const float* x2 = &xsf[(ty * 4 + 2) * 132];
    const float* x3 = &xsf[(ty * 4 + 3) * 132];
#pragma unroll 8
    for (int k = 0; k < 128; ++k) {
        float4 w = ws4[k * 32 + tx];
        float a0 = x0[k], a1 = x1[k], a2 = x2[k], a3 = x3[k];
        acc[0][0] = fmaf(a0, w.x, acc[0][0]); acc[0][1] = fmaf(a0, w.y, acc[0][1]);
        acc[0][2] = fmaf(a0, w.z, acc[0][2]); acc[0][3] = fmaf(a0, w.w, acc[0][3]);
        acc[1][0] = fmaf(a1, w.x, acc[1][0]); acc[1][1] = fmaf(a1, w.y, acc[1][1]);
        acc[1][2] = fmaf(a1, w.z, acc[1][2]); acc[1][3] = fmaf(a1, w.w, acc[1][3]);
        acc[2][0] = fmaf(a2, w.x, acc[2][0]); acc[2][1] = fmaf(a2, w.y, acc[2][1]);
        acc[2][2] = fmaf(a2, w.z, acc[2][2]); acc[2][3] = fmaf(a2, w.w, acc[2][3]);
        acc[3][0] = fmaf(a3, w.x, acc[3][0]); acc[3][1] = fmaf(a3, w.y, acc[3][1]);
        acc[3][2] = fmaf(a3, w.z, acc[3][2]); acc[3][3] = fmaf(a3, w.w, acc[3][3]);
    }
#pragma unroll
    for (int i = 0; i < 4; ++i) {
        int n = n0 + ty * 4 + i;
        if (n < NN) {
            float4 o = make_float4(acc[i][0], acc[i][1], acc[i][2], acc[i][3]);
            ((float4*)(Out + (size_t)n * 128))[tx] = o;
        }
    }
}

// ---------------- SpMM: warp per node; mode 0=build B, 1=iter, 2=final ----------------
__global__ void __launch_bounds__(256) k_spmm(int mode) {
    if (mode == 1 && g_converged) return;
    int n = (blockIdx.x << 3) + (threadIdx.x >> 5);
    int lane = threadIdx.x & 31;
    int beg = g_colptr[n], end = g_colptr[n + 1];
    float4 acc = make_float4(0.f, 0.f, 0.f, 0.f);
    for (int e = beg; e < end; ++e) {
        float v = g_csc_val[e];
        size_t off = ((size_t)g_csc_row[e] << 5) + lane;
        float4 y = ((const float4*)g_Y)[off];
        acc.x = fmaf(v, y.x, acc.x);
        acc.y = fmaf(v, y.y, acc.y);
        acc.z = fmaf(v, y.z, acc.z);
        acc.w = fmaf(v, y.w, acc.w);
    }
    size_t o = ((size_t)n << 5) + lane;
    if (mode == 0) { ((float4*)g_B)[o] = acc; return; }
    float4 b = ((const float4*)g_B)[o];
    acc.x = fmaxf(acc.x + b.x, 0.f);
    acc.y = fmaxf(acc.y + b.y, 0.f);
    acc.z = fmaxf(acc.z + b.z, 0.f);
    acc.w = fmaxf(acc.w + b.w, 0.f);
    float d = 0.f;
    if (mode == 1) {
        float4 xo = ((const float4*)g_X)[o];
        d = fmaxf(fmaxf(fabsf(acc.x - xo.x), fabsf(acc.y - xo.y)),
                  fmaxf(fabsf(acc.z - xo.z), fabsf(acc.w - xo.w)));
    }
    ((float4*)g_X)[o] = acc;
    if (mode == 1) {
#pragma unroll
        for (int s = 16; s; s >>= 1) d = fmaxf(d, __shfl_xor_sync(0xffffffffu, d, s));
        __shared__ float sm[8];
        if (lane == 0) sm[threadIdx.x >> 5] = d;
        __syncthreads();
        if (threadIdx.x == 0) {
            float m = sm[0];
#pragma unroll
            for (int i = 1; i < 8; ++i) m = fmaxf(m, sm[i]);
            atomicMax(&g_err_bits, __float_as_uint(m));
        }
    }
}

__global__ void k_copyBtoX() {
    size_t i = (size_t)blockIdx.x * blockDim.x + threadIdx.x;
    if (i < (size_t)NN * 32) ((float4*)g_X)[i] = ((const float4*)g_B)[i];
}
__global__ void k_reset() { g_converged = 0; g_err_bits = 0u; }
__global__ void k_check() {
    if (!g_converged) {
        if (__uint_as_float(g_err_bits) < FTOL) g_converged = 1;
    }
    g_err_bits = 0u;
}

// ---------------- launch ----------------
extern "C" void kernel_launch(void* const* d_in, const int* in_sizes, int n_in,
                              void* d_out, int out_size) {
    const float* W    = (const float*)d_in[0];
    const float* O1   = (const float*)d_in[1];
    const float* U    = (const float*)d_in[2];
    const float* eval = (const float*)d_in[3];
    const int*   erow = (const int*)d_in[4];
    const int*   ecol = (const int*)d_in[5];
    float* out = (float*)d_out;

    cudaFuncSetAttribute(k_gemm, cudaFuncAttributeMaxDynamicSharedMemorySize, GEMM_SMEM);

    float *pX, *pY, *pO1T, *pWpT;
    cudaGetSymbolAddress((void**)&pX, g_X);
    cudaGetSymbolAddress((void**)&pY, g_Y);
    cudaGetSymbolAddress((void**)&pO1T, g_O1T);
    cudaGetSymbolAddress((void**)&pWpT, g_WpT);

    const int NB_GEMM = (NN + 31) / 32;          // 1563
    const int NB_SPMM = NN / 8;                  // 6250
    dim3 tdim(32, 8);

    // projection + transposes
    k_project<<<128, 128>>>(W);
    k_transpose<<<dim3(4, 4), tdim>>>(O1, pO1T, 128, 128);

    // CSC build
    k_csc_init<<<(NN + 256) / 256, 256>>>();
    k_hist<<<(EE + 255) / 256, 256>>>(ecol);
    k_scan1<<<49, 1024>>>();
    k_scan2<<<1, 1>>>();
    k_scan3<<<49, 1024>>>();
    k_scatter<<<(EE + 255) / 256, 256>>>(erow, ecol, eval);

    // B = (Omega1 @ U @ A)^T  (node-major): U^T -> g_X, gemm -> g_Y, spmm -> g_B
    k_transpose<<<dim3((NN + 31) / 32, 4), tdim>>>(U, pX, 128, NN);
    k_gemm<<<NB_GEMM, 256, GEMM_SMEM>>>(pX, pO1T, pY, 0);
    k_spmm<<<NB_SPMM, 256>>>(0);

    // X = B; reset convergence state
    k_copyBtoX<<<NB_SPMM, 256>>>();
    k_reset<<<1, 1>>>();

    // fixed-point loop (guarded by device convergence flag)
    for (int it = 0; it < 50; ++it) {
        k_gemm<<<NB_GEMM, 256, GEMM_SMEM>>>(pX, pWpT, pY, 1);
        k_spmm<<<NB_SPMM, 256>>>(1);
        k_check<<<1, 1>>>();
    }

    // final recompute: Z = Wp@X@A + B, relu, transpose to (M, N)
    k_gemm<<<NB_GEMM, 256, GEMM_SMEM>>>(pX, pWpT, pY, 0);
    k_spmm<<<NB_SPMM, 256>>>(2);
    k_transpose<<<dim3(4, (NN + 31) / 32), tdim>>>(pX, out, NN, 128);
}